// round 12
// baseline (speedup 1.0000x reference)
#include <cuda_runtime.h>
#include <cuda_bf16.h>
#include <cstdint>

#define N_NODES  50000
#define N_EDGES  800000
#define N_GRAPHS 64
#define IN_DIM   384
#define HID      128
#define MLP_HID  64
#define SCB      196

#define H0_NODES 25088                       // 196*128, 64-divisible
#define H1_NODES (N_NODES - H0_NODES)        // 24912
#define T64_ALL  ((N_NODES + 63) / 64)       // 782
#define T64_H0   (H0_NODES / 64)             // 392
#define T64_H1   ((H1_NODES + 63) / 64)      // 390
#define PB_H0    (H0_NODES / 128)            // 196
#define PB_H1    ((H1_NODES + 127) / 128)    // 195

// smem per stage: A_hi[64][40]bf16=5120, A_lo=5120, B_hi[32][136]=8704, B_lo=8704
#define STG_A_LO 5120
#define STG_B_HI 10240
#define STG_B_LO 18944
#define STG_SZ   27648
#define GEMM_SMEM (2 * STG_SZ)

// ================= streams/events =================
struct HxStreams {
    cudaStream_t s1;
    cudaEvent_t e_root, e_csr, e_g1, eA, eB, eC, eD, eF;
    HxStreams() {
        cudaStreamCreateWithFlags(&s1, cudaStreamNonBlocking);
        cudaEvent_t* evs[8] = {&e_root, &e_csr, &e_g1, &eA, &eB, &eC, &eD, &eF};
        for (int i = 0; i < 8; i++) cudaEventCreateWithFlags(evs[i], cudaEventDisableTiming);
    }
};
static HxStreams g_hx;

// ================= scratch =================
__device__ float g_dis[N_NODES];
__device__ float g_h[N_NODES * HID];
__device__ float g_act[N_NODES * HID];
__device__ float g_pool[N_GRAPHS * HID];
__device__ float g_cnt[N_GRAPHS];
__device__ int   g_cntarr[N_NODES];
__device__ int   g_scan[N_NODES];
__device__ int   g_bsum[256];
__device__ int   g_boff[256];
__device__ int   g_rowptr[N_NODES + 1];
__device__ int   g_cursor[N_NODES];
__device__ int   g_csrc[N_EDGES];

__device__ __forceinline__ uint32_t smem_u32(const void* p) {
    uint32_t a;
    asm("{ .reg .u64 t; cvta.to.shared.u64 t, %1; cvt.u32.u64 %0, t; }" : "=r"(a) : "l"(p));
    return a;
}

// pack (f0,f1) -> bf16x2 hi + residual lo
__device__ __forceinline__ void split2(float f0, float f1, uint32_t& h, uint32_t& l) {
    asm("cvt.rn.bf16x2.f32 %0, %1, %2;" : "=r"(h) : "f"(f1), "f"(f0));
    float h0 = __uint_as_float(h << 16);
    float h1 = __uint_as_float(h & 0xFFFF0000u);
    float l0 = f0 - h0, l1 = f1 - h1;
    asm("cvt.rn.bf16x2.f32 %0, %1, %2;" : "=r"(l) : "f"(l1), "f"(l0));
}

#define LDSM_X4(r, a)                                                          \
    asm volatile("ldmatrix.sync.aligned.m8n8.x4.shared.b16 {%0,%1,%2,%3}, [%4];" \
                 : "=r"((r)[0]), "=r"((r)[1]), "=r"((r)[2]), "=r"((r)[3]) : "r"(a))
#define LDSM_X4T(r, a)                                                         \
    asm volatile("ldmatrix.sync.aligned.m8n8.x4.trans.shared.b16 {%0,%1,%2,%3}, [%4];" \
                 : "=r"((r)[0]), "=r"((r)[1]), "=r"((r)[2]), "=r"((r)[3]) : "r"(a))
#define MMA_BF16(c, a, b0, b1)                                                 \
    asm volatile("mma.sync.aligned.m16n8k16.row.col.f32.bf16.bf16.f32 "        \
                 "{%0,%1,%2,%3}, {%4,%5,%6,%7}, {%8,%9}, {%0,%1,%2,%3};"       \
                 : "+f"((c)[0]), "+f"((c)[1]), "+f"((c)[2]), "+f"((c)[3])      \
                 : "r"((a)[0]), "r"((a)[1]), "r"((a)[2]), "r"((a)[3]),         \
                   "r"(b0), "r"(b1))

// ================= setup kernels =================
__global__ void k_zero() {
    int i = blockIdx.x * blockDim.x + threadIdx.x;
    if (i < N_NODES)        g_cntarr[i] = 0;
    if (i < N_GRAPHS * HID) g_pool[i] = 0.f;
    if (i < N_GRAPHS)       g_cnt[i] = 0.f;
}
__global__ void k_count_edges(const int* __restrict__ dst) {
    int e = blockIdx.x * blockDim.x + threadIdx.x;
    if (e < N_EDGES) atomicAdd(&g_cntarr[dst[e]], 1);
}
__global__ void k_scan1() {
    __shared__ int s[256];
    int tid = threadIdx.x;
    int i = blockIdx.x * 256 + tid;
    s[tid] = (i < N_NODES) ? g_cntarr[i] : 0;
    __syncthreads();
#pragma unroll
    for (int off = 1; off < 256; off <<= 1) {
        int t = (tid >= off) ? s[tid - off] : 0;
        __syncthreads();
        s[tid] += t;
        __syncthreads();
    }
    if (i < N_NODES) g_scan[i] = s[tid];
    if (tid == 255) g_bsum[blockIdx.x] = s[255];
}
__global__ void k_scan2() {
    __shared__ int s[256];
    int tid = threadIdx.x;
    int v = (tid < SCB) ? g_bsum[tid] : 0;
    s[tid] = v;
    __syncthreads();
#pragma unroll
    for (int off = 1; off < 256; off <<= 1) {
        int t = (tid >= off) ? s[tid - off] : 0;
        __syncthreads();
        s[tid] += t;
        __syncthreads();
    }
    g_boff[tid] = s[tid] - v;
}
__global__ void k_scan3() {
    int i = blockIdx.x * blockDim.x + threadIdx.x;
    if (i < N_NODES) {
        int cnt = g_cntarr[i];
        int S = g_scan[i] + g_boff[i >> 8];
        g_rowptr[i + 1] = S;
        g_cursor[i] = S - cnt;
        g_dis[i] = rsqrtf((float)cnt + 1.f);
        if (i == 0) g_rowptr[0] = 0;
    }
}
__global__ void k_fill(const int* __restrict__ src, const int* __restrict__ dst) {
    int e = blockIdx.x * blockDim.x + threadIdx.x;
    if (e < N_EDGES) {
        int d = dst[e];
        int pos = atomicAdd(&g_cursor[d], 1);
        g_csrc[pos] = src[e];
    }
}

// ================= split-bf16 mma.sync GEMM (64-row CTA tile) =================
// CTA 64x128, 256 threads, warp grid 2m x 4n, warp tile 32x32 (m16n8k16), 2 CTAs/SM.
// Each thread stages 8 floats of A and 16 floats of B (rows br and br+16).
template <int K, bool FOLD_DIS>
__global__ void __launch_bounds__(256)
k_gemm(const float* __restrict__ Aext, const float* __restrict__ W, int m0base) {
    extern __shared__ char smx[];
    const float* A = Aext ? Aext : g_act;

    const int tid = threadIdx.x;
    const int lane = tid & 31;
    const int wid = tid >> 5;           // 0..7
    const int wm = wid & 1;             // 2 m-warps * 32 rows
    const int wn = wid >> 1;            // 4 n-warps * 32 cols
    const int m0 = m0base + blockIdx.x * 64;

    const int ar = tid >> 2;            // A row 0..63
    const int ac = (tid & 3) * 8;       // A col (within 32-chunk)
    const int br = tid >> 4;            // B row 0..15 (also handles br+16)
    const int bc = (tid & 15) * 8;      // B col 0..120

    const uint32_t sbase = smem_u32(smx);

    float4 sa0, sa1, sb0, sb1, sb2, sb3;

    auto ldg_chunk = [&](int k0) {
        int row = m0 + ar;
        int rc = (row < N_NODES) ? row : (N_NODES - 1);
        const float* ap = A + (long)rc * K + k0 + ac;
        sa0 = *(const float4*)ap;
        sa1 = *(const float4*)(ap + 4);
        const float* bp = W + (long)(k0 + br) * 128 + bc;
        sb0 = *(const float4*)bp;
        sb1 = *(const float4*)(bp + 4);
        const float* bp2 = W + (long)(k0 + br + 16) * 128 + bc;
        sb2 = *(const float4*)bp2;
        sb3 = *(const float4*)(bp2 + 4);
    };
    auto sts_chunk = [&](int s) {
        char* base = smx + s * STG_SZ;
        uint32_t h0, h1, h2, h3, l0, l1, l2, l3;
        split2(sa0.x, sa0.y, h0, l0); split2(sa0.z, sa0.w, h1, l1);
        split2(sa1.x, sa1.y, h2, l2); split2(sa1.z, sa1.w, h3, l3);
        *(uint4*)(base + (ar * 40 + ac) * 2)            = make_uint4(h0, h1, h2, h3);
        *(uint4*)(base + STG_A_LO + (ar * 40 + ac) * 2) = make_uint4(l0, l1, l2, l3);
        split2(sb0.x, sb0.y, h0, l0); split2(sb0.z, sb0.w, h1, l1);
        split2(sb1.x, sb1.y, h2, l2); split2(sb1.z, sb1.w, h3, l3);
        *(uint4*)(base + STG_B_HI + (br * 136 + bc) * 2) = make_uint4(h0, h1, h2, h3);
        *(uint4*)(base + STG_B_LO + (br * 136 + bc) * 2) = make_uint4(l0, l1, l2, l3);
        split2(sb2.x, sb2.y, h0, l0); split2(sb2.z, sb2.w, h1, l1);
        split2(sb3.x, sb3.y, h2, l2); split2(sb3.z, sb3.w, h3, l3);
        *(uint4*)(base + STG_B_HI + ((br + 16) * 136 + bc) * 2) = make_uint4(h0, h1, h2, h3);
        *(uint4*)(base + STG_B_LO + ((br + 16) * 136 + bc) * 2) = make_uint4(l0, l1, l2, l3);
    };

    float c[2][4][4] = {};

    constexpr int NC = K / 32;
    ldg_chunk(0);
    sts_chunk(0);
    __syncthreads();
    if (NC > 1) ldg_chunk(32);

    for (int ch = 0; ch < NC; ch++) {
        if (ch + 1 < NC) sts_chunk((ch + 1) & 1);
        if (ch + 2 < NC) ldg_chunk((ch + 2) * 32);

        uint32_t st = sbase + (ch & 1) * STG_SZ;
#pragma unroll
        for (int ks = 0; ks < 2; ks++) {
            uint32_t Ah[2][4], Al[2][4], Bh[2][4], Bl[2][4];
#pragma unroll
            for (int mt = 0; mt < 2; mt++) {
                uint32_t row = wm * 32 + mt * 16 + (lane & 15);
                uint32_t col = ks * 16 + (lane >> 4) * 8;
                uint32_t ad = st + (row * 40 + col) * 2;
                LDSM_X4(Ah[mt], ad);
                LDSM_X4(Al[mt], ad + STG_A_LO);
            }
#pragma unroll
            for (int g2 = 0; g2 < 2; g2++) {
                uint32_t brow = ks * 16 + (lane & 15);
                uint32_t bcol = wn * 32 + g2 * 16 + (lane >> 4) * 8;
                uint32_t bd = st + STG_B_HI + (brow * 136 + bcol) * 2;
                LDSM_X4T(Bh[g2], bd);
                LDSM_X4T(Bl[g2], bd + (STG_B_LO - STG_B_HI));
            }
#pragma unroll
            for (int mt = 0; mt < 2; mt++)
#pragma unroll
                for (int nt = 0; nt < 4; nt++) {
                    uint32_t b0h = Bh[nt >> 1][(nt & 1) * 2], b1h = Bh[nt >> 1][(nt & 1) * 2 + 1];
                    uint32_t b0l = Bl[nt >> 1][(nt & 1) * 2], b1l = Bl[nt >> 1][(nt & 1) * 2 + 1];
                    MMA_BF16(c[mt][nt], Ah[mt], b0h, b1h);
                    MMA_BF16(c[mt][nt], Ah[mt], b0l, b1l);
                    MMA_BF16(c[mt][nt], Al[mt], b0h, b1h);
                }
        }
        __syncthreads();
    }

    const int g = lane >> 2, t = lane & 3;
#pragma unroll
    for (int mt = 0; mt < 2; mt++) {
        int r0 = m0 + wm * 32 + mt * 16 + g;
        int r1 = r0 + 8;
        float s0 = 1.f, s1 = 1.f;
        if (FOLD_DIS) {
            if (r0 < N_NODES) s0 = g_dis[r0];
            if (r1 < N_NODES) s1 = g_dis[r1];
        }
#pragma unroll
        for (int nt = 0; nt < 4; nt++) {
            int col = wn * 32 + nt * 8 + t * 2;
            if (r0 < N_NODES)
                *(float2*)&g_h[r0 * 128 + col] = make_float2(c[mt][nt][0] * s0, c[mt][nt][1] * s0);
            if (r1 < N_NODES)
                *(float2*)&g_h[r1 * 128 + col] = make_float2(c[mt][nt][2] * s1, c[mt][nt][3] * s1);
        }
    }
}

// ================= CSR aggregation: warp per node =================
template <bool WEIGHTED>
__global__ void __launch_bounds__(256)
k_agg(const float* __restrict__ bias, int base, int ncount) {
    int wid = threadIdx.x >> 5;
    int lane = threadIdx.x & 31;
    int node = base + blockIdx.x * 8 + wid;
    if (node >= base + ncount) return;

    int rp0 = g_rowptr[node];
    int rp1 = g_rowptr[node + 1];
    float dn = g_dis[node];
    int l4 = lane * 4;

    float4 acc = *(const float4*)&g_h[node * 128 + l4];
    if (WEIGHTED) { acc.x *= dn; acc.y *= dn; acc.z *= dn; acc.w *= dn; }

    int i = rp0;
    if (WEIGHTED) {
        for (; i + 1 < rp1; i += 2) {
            int s0 = g_csrc[i], s1 = g_csrc[i + 1];
            float w0 = g_dis[s0], w1 = g_dis[s1];
            float4 v0 = *(const float4*)&g_h[s0 * 128 + l4];
            float4 v1 = *(const float4*)&g_h[s1 * 128 + l4];
            acc.x += v0.x * w0 + v1.x * w1;
            acc.y += v0.y * w0 + v1.y * w1;
            acc.z += v0.z * w0 + v1.z * w1;
            acc.w += v0.w * w0 + v1.w * w1;
        }
        if (i < rp1) {
            int s0 = g_csrc[i];
            float w0 = g_dis[s0];
            float4 v0 = *(const float4*)&g_h[s0 * 128 + l4];
            acc.x += v0.x * w0; acc.y += v0.y * w0;
            acc.z += v0.z * w0; acc.w += v0.w * w0;
        }
    } else {
        for (; i + 3 < rp1; i += 4) {
            int s0 = g_csrc[i], s1 = g_csrc[i + 1], s2 = g_csrc[i + 2], s3 = g_csrc[i + 3];
            float4 v0 = *(const float4*)&g_h[s0 * 128 + l4];
            float4 v1 = *(const float4*)&g_h[s1 * 128 + l4];
            float4 v2 = *(const float4*)&g_h[s2 * 128 + l4];
            float4 v3 = *(const float4*)&g_h[s3 * 128 + l4];
            acc.x += (v0.x + v1.x) + (v2.x + v3.x);
            acc.y += (v0.y + v1.y) + (v2.y + v3.y);
            acc.z += (v0.z + v1.z) + (v2.z + v3.z);
            acc.w += (v0.w + v1.w) + (v2.w + v3.w);
        }
        for (; i < rp1; i++) {
            int s0 = g_csrc[i];
            float4 v0 = *(const float4*)&g_h[s0 * 128 + l4];
            acc.x += v0.x; acc.y += v0.y; acc.z += v0.z; acc.w += v0.w;
        }
    }

    float4 b = *(const float4*)&bias[l4];
    acc.x = fmaxf(fmaf(acc.x, dn, b.x), 0.f);
    acc.y = fmaxf(fmaf(acc.y, dn, b.y), 0.f);
    acc.z = fmaxf(fmaf(acc.z, dn, b.z), 0.f);
    acc.w = fmaxf(fmaf(acc.w, dn, b.w), 0.f);
    *(float4*)&g_act[node * 128 + l4] = acc;
}

// ================= pooling (half-range) + MLP =================
__global__ void __launch_bounds__(128)
k_poolseg(const int* __restrict__ batch, int nodebase) {
    __shared__ int sb[128];
    int t = threadIdx.x;
    int n0 = nodebase + blockIdx.x * 128;
    int cnt = min(128, N_NODES - n0);
    if (t < cnt) sb[t] = batch[n0 + t];
    __syncthreads();

    float acc = 0.f;
    int cur = sb[0];
    int segstart = 0;
    for (int i = 0; i < cnt; i++) {
        int g = sb[i];
        if (g != cur) {
            atomicAdd(&g_pool[cur * 128 + t], acc);
            if (t == 0) atomicAdd(&g_cnt[cur], (float)(i - segstart));
            acc = 0.f;
            cur = g;
            segstart = i;
        }
        acc += g_act[(n0 + i) * 128 + t];
    }
    atomicAdd(&g_pool[cur * 128 + t], acc);
    if (t == 0) atomicAdd(&g_cnt[cur], (float)(cnt - segstart));
}

__global__ void k_mlp(const float* __restrict__ Wm1, const float* __restrict__ bm1,
                      const float* __restrict__ Wm2, const float* __restrict__ bm2,
                      float* __restrict__ out) {
    int g = blockIdx.x;
    int j = threadIdx.x;
    __shared__ float p[128];
    __shared__ float red[64];
    float cnt = fmaxf(g_cnt[g], 1.f);
    p[j] = g_pool[g * 128 + j] / cnt;
    p[j + 64] = g_pool[g * 128 + 64 + j] / cnt;
    __syncthreads();
    float z = bm1[j];
#pragma unroll 8
    for (int k = 0; k < 128; k++) z = fmaf(p[k], Wm1[k * 64 + j], z);
    z = fmaxf(z, 0.f);
    z *= Wm2[j];
    red[j] = z;
    __syncthreads();
#pragma unroll
    for (int s = 32; s > 0; s >>= 1) {
        if (j < s) red[j] += red[j + s];
        __syncthreads();
    }
    if (j == 0) out[g] = red[0] + bm2[0];
}

// ================= launch =================
extern "C" void kernel_launch(void* const* d_in, const int* in_sizes, int n_in,
                              void* d_out, int out_size) {
    const float* x    = (const float*)d_in[0];
    const int*   ei   = (const int*)  d_in[1];
    const int*   batch= (const int*)  d_in[2];
    const float* W1   = (const float*)d_in[3];
    const float* b1   = (const float*)d_in[4];
    const float* W2   = (const float*)d_in[5];
    const float* b2   = (const float*)d_in[6];
    const float* W3   = (const float*)d_in[7];
    const float* b3   = (const float*)d_in[8];
    const float* Wm1  = (const float*)d_in[9];
    const float* bm1  = (const float*)d_in[10];
    const float* Wm2  = (const float*)d_in[11];
    const float* bm2  = (const float*)d_in[12];
    const int* src = ei;
    const int* dst = ei + N_EDGES;
    float* out = (float*)d_out;
    cudaStream_t s1 = g_hx.s1;

    cudaFuncSetAttribute(k_gemm<IN_DIM, false>, cudaFuncAttributeMaxDynamicSharedMemorySize, GEMM_SMEM);
    cudaFuncSetAttribute(k_gemm<HID, true>,     cudaFuncAttributeMaxDynamicSharedMemorySize, GEMM_SMEM);

    const int EB  = (N_EDGES + 255) / 256;
    const int AB0 = (H0_NODES + 7) / 8;
    const int AB1 = (H1_NODES + 7) / 8;

    // ---- fork: CSR build on s1 || layer-1 GEMM on stream 0 ----
    cudaEventRecord(g_hx.e_root, 0);
    cudaStreamWaitEvent(s1, g_hx.e_root, 0);

    k_zero       <<<SCB, 256, 0, s1>>>();
    k_count_edges<<<EB, 256, 0, s1>>>(dst);
    k_scan1      <<<SCB, 256, 0, s1>>>();
    k_scan2      <<<1, 256, 0, s1>>>();
    k_scan3      <<<SCB, 256, 0, s1>>>();
    k_fill       <<<EB, 256, 0, s1>>>(src, dst);
    cudaEventRecord(g_hx.e_csr, s1);

    k_gemm<IN_DIM, false><<<T64_ALL, 256, GEMM_SMEM>>>(x, W1, 0);
    cudaEventRecord(g_hx.e_g1, 0);

    cudaStreamWaitEvent(0, g_hx.e_csr, 0);
    cudaStreamWaitEvent(s1, g_hx.e_g1, 0);

    // ---- layer 1 agg + layer 2 gemm, half-pipelined ----
    k_agg<true><<<AB0, 256>>>(b1, 0, H0_NODES);
    k_gemm<HID, true><<<T64_H0, 256, GEMM_SMEM>>>(nullptr, W2, 0);
    cudaEventRecord(g_hx.eA, 0);
    k_agg<true><<<AB1, 256, 0, s1>>>(b1, H0_NODES, H1_NODES);
    k_gemm<HID, true><<<T64_H1, 256, GEMM_SMEM, s1>>>(nullptr, W2, H0_NODES);
    cudaEventRecord(g_hx.eB, s1);
    cudaStreamWaitEvent(0, g_hx.eB, 0);
    cudaStreamWaitEvent(s1, g_hx.eA, 0);

    // ---- layer 2 agg + layer 3 gemm ----
    k_agg<false><<<AB0, 256>>>(b2, 0, H0_NODES);
    k_gemm<HID, true><<<T64_H0, 256, GEMM_SMEM>>>(nullptr, W3, 0);
    cudaEventRecord(g_hx.eC, 0);
    k_agg<false><<<AB1, 256, 0, s1>>>(b2, H0_NODES, H1_NODES);
    k_gemm<HID, true><<<T64_H1, 256, GEMM_SMEM, s1>>>(nullptr, W3, H0_NODES);
    cudaEventRecord(g_hx.eD, s1);
    cudaStreamWaitEvent(0, g_hx.eD, 0);
    cudaStreamWaitEvent(s1, g_hx.eC, 0);

    // ---- layer 3 agg + pooling, per-half chained ----
    k_agg<false><<<AB0, 256>>>(b3, 0, H0_NODES);
    k_poolseg<<<PB_H0, 128>>>(batch, 0);
    k_agg<false><<<AB1, 256, 0, s1>>>(b3, H0_NODES, H1_NODES);
    k_poolseg<<<PB_H1, 128, 0, s1>>>(batch, H0_NODES);
    cudaEventRecord(g_hx.eF, s1);
    cudaStreamWaitEvent(0, g_hx.eF, 0);

    // ---- MLP ----
    k_mlp<<<N_GRAPHS, 64>>>(Wm1, bm1, Wm2, bm2, out);
}